// round 2
// baseline (speedup 1.0000x reference)
#include <cuda_runtime.h>
#include <cstddef>

// Problem constants (fixed by the reference):
//   B = 65536 tasks, S = 128 labels/task, C = 10 classes, STATS = 14, D = 256
#define TASKS_PER_BLOCK 64
#define NTHREADS        256
#define KC              16      // w2 k-tile
#define DDIM            256
#define SDIM            14

// Dynamic smem layout (floats unless noted):
//   h1T   : [256][64]  = 16384 f  (h1 transposed: h1T[k][t])
//   buf   : 4096 f     (phase2: w1[14][256]=3584 + b1=256 ; phase3: w2 tile [KC][256])
//   stats : [64][17]   = 1088 f   (padded row stride 17 -> conflict-free)
//   part  : [64][4] u64 = 2048 B  (packed per-sub-thread histograms)
#define H1T_F    (256 * 64)
#define BUF_F    4096
#define STATS_F  (64 * 17)
#define SMEM_BYTES ((H1T_F + BUF_F + STATS_F) * 4 + 64 * 4 * 8)

__global__ __launch_bounds__(NTHREADS, 2)
void tte_fused_kernel(const int*   __restrict__ y,
                      const float* __restrict__ w1,
                      const float* __restrict__ b1,
                      const float* __restrict__ w2,
                      const float* __restrict__ b2,
                      float*       __restrict__ out)
{
    extern __shared__ float smem[];
    float* h1T    = smem;                 // [k*64 + t]
    float* buf    = h1T + H1T_F;
    float* statsS = buf + BUF_F;          // [t*17 + j]
    unsigned long long* part =
        (unsigned long long*)(statsS + STATS_F);   // [t*4 + sub]

    const int tid   = threadIdx.x;
    const int task0 = blockIdx.x * TASKS_PER_BLOCK;

    // ---------------- Phase 0: stage w1 + b1 into smem buf ----------------
    // buf[0..3583] = w1 (row-major [14][256]), buf[3584..3839] = b1
    for (int i = tid; i < SDIM * DDIM + DDIM; i += NTHREADS)
        buf[i] = (i < SDIM * DDIM) ? w1[i] : b1[i - SDIM * DDIM];

    // ---------------- Phase 1: packed histograms ----------------
    {
        const int t   = tid >> 2;          // task within block (0..63)
        const int sub = tid & 3;           // quarter of the 128 labels
        const int4* yp = (const int4*)(y + ((size_t)(task0 + t) * 128 + sub * 32));
        unsigned long long h = 0ULL;       // 10 classes x 6-bit counts
        #pragma unroll
        for (int i = 0; i < 8; ++i) {
            int4 v = yp[i];
            h += (1ULL << (6 * v.x)) + (1ULL << (6 * v.y))
               + (1ULL << (6 * v.z)) + (1ULL << (6 * v.w));
        }
        part[t * 4 + sub] = h;
    }
    __syncthreads();

    // ---------------- Phase 1b: stats (64 threads, one task each) ----------------
    if (tid < TASKS_PER_BLOCK) {
        const unsigned long long p0 = part[tid * 4 + 0];
        const unsigned long long p1 = part[tid * 4 + 1];
        const unsigned long long p2 = part[tid * 4 + 2];
        const unsigned long long p3 = part[tid * 4 + 3];
        float pmax = 0.0f, ent = 0.0f;
        int nnz = 0;
        float* st = &statsS[tid * 17];
        #pragma unroll
        for (int c = 0; c < 10; ++c) {
            const int sh = 6 * c;
            int cnt = (int)((p0 >> sh) & 63ULL) + (int)((p1 >> sh) & 63ULL)
                    + (int)((p2 >> sh) & 63ULL) + (int)((p3 >> sh) & 63ULL);
            float p = (float)cnt * (1.0f / 128.0f);   // total is exactly 128
            st[c] = p;
            pmax = fmaxf(pmax, p);
            nnz += (cnt > 0);
            ent -= p * logf(p + 1e-6f);
        }
        st[10] = (float)nnz;
        st[11] = ent;
        st[12] = 128.0f;
        st[13] = pmax;
    }
    __syncthreads();

    // ---------------- Phase 2: h1T[k][t] = GELU(stats[t] . w1[:,k] + b1[k]) ----------------
    // 16384 entries / 256 threads = 64 per thread. Within a warp k is uniform
    // (broadcast w1 reads), t consecutive (conflict-free h1T writes).
    #pragma unroll 4
    for (int i = 0; i < 64; ++i) {
        const int idx = i * NTHREADS + tid;
        const int k = idx >> 6;
        const int t = idx & 63;
        const float* st = &statsS[t * 17];
        float v = buf[SDIM * DDIM + k];              // b1[k]
        #pragma unroll
        for (int j = 0; j < SDIM; ++j)
            v = fmaf(st[j], buf[j * DDIM + k], v);
        // exact GELU: 0.5*x*(1+erf(x/sqrt(2)))
        h1T[k * 64 + t] = 0.5f * v * (1.0f + erff(v * 0.70710678118654752f));
    }
    // (no sync here: the kk-loop leading sync both finishes phase 2's buf reads
    //  and h1T writes before buf is overwritten / h1T is read)

    // ---------------- Phase 3: out = h1 @ w2 + b2, 8x8 register tiles ----------------
    const int tcol = tid & 31;    // 32 col-threads * 8 cols  = 256 cols
    const int trow = tid >> 5;    // 8 task-threads * 8 tasks = 64 tasks

    float acc[8][8];
    #pragma unroll
    for (int a = 0; a < 8; ++a)
        #pragma unroll
        for (int b = 0; b < 8; ++b) acc[a][b] = 0.0f;

    for (int kk = 0; kk < DDIM; kk += KC) {
        __syncthreads();
        // Stage w2[kk..kk+KC)[0..256) : a contiguous 4096-float chunk
        const float4* src = (const float4*)(w2 + (size_t)kk * DDIM);
        float4*       dst = (float4*)buf;
        #pragma unroll
        for (int i = 0; i < 4; ++i)
            dst[tid + NTHREADS * i] = src[tid + NTHREADS * i];
        __syncthreads();

        #pragma unroll
        for (int r = 0; r < KC; ++r) {
            const float* arow = &h1T[(kk + r) * 64 + trow * 8];   // warp-broadcast
            const float* brow = &buf[r * DDIM + tcol * 8];        // conflict-free
            float av[8], bv[8];
            *(float4*)&av[0] = *(const float4*)&arow[0];
            *(float4*)&av[4] = *(const float4*)&arow[4];
            *(float4*)&bv[0] = *(const float4*)&brow[0];
            *(float4*)&bv[4] = *(const float4*)&brow[4];
            #pragma unroll
            for (int a = 0; a < 8; ++a)
                #pragma unroll
                for (int b = 0; b < 8; ++b)
                    acc[a][b] = fmaf(av[a], bv[b], acc[a][b]);
        }
    }

    // ---------------- Epilogue: + b2, coalesced float4 stores ----------------
    float bb[8];
    *(float4*)&bb[0] = *(const float4*)&b2[tcol * 8];
    *(float4*)&bb[4] = *(const float4*)&b2[tcol * 8 + 4];
    #pragma unroll
    for (int a = 0; a < 8; ++a) {
        const int row = task0 + trow * 8 + a;
        float4* op = (float4*)(out + (size_t)row * DDIM + tcol * 8);
        float4 o0, o1;
        o0.x = acc[a][0] + bb[0]; o0.y = acc[a][1] + bb[1];
        o0.z = acc[a][2] + bb[2]; o0.w = acc[a][3] + bb[3];
        o1.x = acc[a][4] + bb[4]; o1.y = acc[a][5] + bb[5];
        o1.z = acc[a][6] + bb[6]; o1.w = acc[a][7] + bb[7];
        op[0] = o0;
        op[1] = o1;
    }
}

extern "C" void kernel_launch(void* const* d_in, const int* in_sizes, int n_in,
                              void* d_out, int out_size)
{
    const int*   y  = (const int*)  d_in[0];
    const float* w1 = (const float*)d_in[1];
    const float* b1 = (const float*)d_in[2];
    const float* w2 = (const float*)d_in[3];
    const float* b2 = (const float*)d_in[4];
    float* out = (float*)d_out;

    const int B    = in_sizes[0] / 128;          // tasks
    const int grid = B / TASKS_PER_BLOCK;        // 1024 for B=65536

    cudaFuncSetAttribute(tte_fused_kernel,
                         cudaFuncAttributeMaxDynamicSharedMemorySize,
                         SMEM_BYTES);

    tte_fused_kernel<<<grid, NTHREADS, SMEM_BYTES>>>(y, w1, b1, w2, b2, out);
}

// round 7
// speedup vs baseline: 1.4994x; 1.4994x over previous
#include <cuda_runtime.h>
#include <cstdint>
#include <cstddef>

#define THREADS 256
#define TASKS   128          // tasks per CTA (M)
#define DDIM    256          // N, and K of stage-2
#define SDIM    14
#define KCH     16           // stage-2 K chunk
#define NCHUNK  (DDIM / KCH) // 16
#define ASTRIDE 260          // A smem row stride (floats) -> conflict-free A frags
#define BSTRIDE 264          // B smem row stride (floats) -> conflict-free B frags

// w2 pre-rounded to tf32 (rna), plain [k][n] row-major.
__device__ float g_w2r[DDIM * DDIM];

// ---- smem layout (floats) ----
#define A_OFF    0
#define A_FLOATS (TASKS * ASTRIDE)                 // 33280
#define B_OFF    (A_OFF + A_FLOATS)
#define B_FLOATS (2 * KCH * BSTRIDE)               // 8448
#define W1_OFF   (B_OFF + B_FLOATS)
#define B1_OFF   (W1_OFF + SDIM * DDIM)
#define B2_OFF   (B1_OFF + DDIM)
#define ST_OFF   (B2_OFF + DDIM)                   // stats, stride 17
#define PART_OFF (ST_OFF + 128 * 17)               // 128*4 u64 = 1024 floats
#define SMEM_FLOATS (PART_OFF + 1024)
#define SMEM_BYTES  (SMEM_FLOATS * 4)              // 196096 B

static __device__ __forceinline__ uint32_t smem_u32(const void* p) {
    uint32_t a;
    asm("{ .reg .u64 t; cvta.to.shared.u64 t, %1; cvt.u32.u64 %0, t; }"
        : "=r"(a) : "l"(p));
    return a;
}
static __device__ __forceinline__ uint32_t f2tf32(float x) {
    uint32_t u; asm("cvt.rna.tf32.f32 %0, %1;" : "=r"(u) : "f"(x)); return u;
}
static __device__ __forceinline__ void mma_tf32(float* c,
        uint32_t a0, uint32_t a1, uint32_t a2, uint32_t a3,
        uint32_t b0, uint32_t b1) {
    asm volatile("mma.sync.aligned.m16n8k8.row.col.f32.tf32.tf32.f32 "
                 "{%0,%1,%2,%3}, {%4,%5,%6,%7}, {%8,%9}, {%0,%1,%2,%3};"
                 : "+f"(c[0]), "+f"(c[1]), "+f"(c[2]), "+f"(c[3])
                 : "r"(a0), "r"(a1), "r"(a2), "r"(a3), "r"(b0), "r"(b1));
}

// ---- prep kernel: rna-round w2 into g_w2r ----
__global__ void w2_round(const float* __restrict__ w2) {
    int i = blockIdx.x * 256 + threadIdx.x;
    g_w2r[i] = __uint_as_float(f2tf32(w2[i]));
}

// issue cp.async for B chunk c into buffer `buf` (16 rows x 256 floats)
static __device__ __forceinline__ void prefetch_chunk(uint32_t smb, int c, int buf, int tid) {
    const uint32_t dst0 = smb + (uint32_t)(B_OFF + buf * KCH * BSTRIDE) * 4u;
    const float* src = g_w2r + (size_t)c * KCH * DDIM;
#pragma unroll
    for (int i = 0; i < 4; ++i) {
        int idx = i * THREADS + tid;          // 0..1023 float4s
        int r = idx >> 6;                     // row 0..15
        int q = idx & 63;                     // float4 within row
        uint32_t d = dst0 + (uint32_t)(r * BSTRIDE + q * 4) * 4u;
        const float* s = src + r * DDIM + q * 4;
        asm volatile("cp.async.ca.shared.global [%0], [%1], 16;" :: "r"(d), "l"(s));
    }
    asm volatile("cp.async.commit_group;" ::: "memory");
}

__global__ __launch_bounds__(THREADS, 1)
void tte_main(const int*   __restrict__ y,
              const float* __restrict__ w1,
              const float* __restrict__ b1,
              const float* __restrict__ w2,
              const float* __restrict__ b2,
              float*       __restrict__ out)
{
    extern __shared__ float sm[];
    const uint32_t smb = smem_u32(sm);

    float* w1s    = sm + W1_OFF;
    float* b1s    = sm + B1_OFF;
    float* b2s    = sm + B2_OFF;
    float* statsS = sm + ST_OFF;
    unsigned long long* part = (unsigned long long*)(sm + PART_OFF);
    uint32_t* Asm = (uint32_t*)(sm + A_OFF);

    const int tid  = threadIdx.x;
    const int wid  = tid >> 5, lane = tid & 31;
    const int g    = lane >> 2, tig = lane & 3;     // mma groupID / thread-in-group
    const int wr   = wid & 3,  wc  = wid >> 2;      // warp row-group(32) / col-half(128)

    // ---- prefetch B chunks 0,1 immediately (overlaps everything below) ----
    prefetch_chunk(smb, 0, 0, tid);
    prefetch_chunk(smb, 1, 1, tid);

    // ---- small params ----
    for (int i = tid; i < SDIM * DDIM; i += THREADS) w1s[i] = w1[i];
    if (tid < DDIM) { b1s[tid] = b1[tid]; b2s[tid] = b2[tid]; }

    // ---- histogram: thread (t, hh) counts 64 labels, 8-bit packed ----
    {
        const int t = tid & 127, hh = tid >> 7;
        const int4* yp = (const int4*)(y + ((size_t)blockIdx.x * TASKS + t) * 128 + hh * 64);
        unsigned long long h0 = 0ull, h1v = 0ull;
#pragma unroll
        for (int i = 0; i < 16; ++i) {
            int4 v = yp[i];
            { int c = v.x; unsigned long long o = 1ull << ((c & 7) * 8); if (c < 8) h0 += o; else h1v += o; }
            { int c = v.y; unsigned long long o = 1ull << ((c & 7) * 8); if (c < 8) h0 += o; else h1v += o; }
            { int c = v.z; unsigned long long o = 1ull << ((c & 7) * 8); if (c < 8) h0 += o; else h1v += o; }
            { int c = v.w; unsigned long long o = 1ull << ((c & 7) * 8); if (c < 8) h0 += o; else h1v += o; }
        }
        part[t * 4 + hh * 2 + 0] = h0;
        part[t * 4 + hh * 2 + 1] = h1v;
    }
    __syncthreads();

    // ---- stats (threads 0..127, one task each) ----
    if (tid < 128) {
        const unsigned long long a0 = part[tid * 4 + 0], a1 = part[tid * 4 + 1];
        const unsigned long long c0 = part[tid * 4 + 2], c1 = part[tid * 4 + 3];
        float pmax = 0.0f, ent = 0.0f; int nnz = 0;
        float* st = &statsS[tid * 17];
#pragma unroll
        for (int c = 0; c < 10; ++c) {
            int cnt;
            if (c < 8) cnt = (int)((a0 >> (8 * c)) & 255ull) + (int)((c0 >> (8 * c)) & 255ull);
            else       cnt = (int)((a1 >> (8 * (c - 8))) & 255ull) + (int)((c1 >> (8 * (c - 8))) & 255ull);
            float p = (float)cnt * (1.0f / 128.0f);     // total is exactly 128
            st[c] = p;
            pmax = fmaxf(pmax, p);
            nnz += (cnt > 0);
            ent -= p * logf(p + 1e-6f);
        }
        st[10] = (float)nnz; st[11] = ent; st[12] = 128.0f; st[13] = pmax;
    }
    __syncthreads();

    // ---- stage 1: exact fp32 FFMA + GELU -> tf32(rna) -> A smem [t][k] ----
    {
        const int t = tid & 127, hh = tid >> 7;     // k-half per thread
        float st[SDIM];
#pragma unroll
        for (int i = 0; i < SDIM; ++i) st[i] = statsS[t * 17 + i];
        uint32_t* arow = Asm + t * ASTRIDE + hh * 128;
#pragma unroll 4
        for (int j = 0; j < 128; ++j) {
            const int k = hh * 128 + j;
            float v = b1s[k];
#pragma unroll
            for (int i = 0; i < SDIM; ++i) v = fmaf(st[i], w1s[i * DDIM + k], v);
            float gl = 0.5f * v * (1.0f + erff(v * 0.70710678118654752f));
            arow[j] = f2tf32(gl);
        }
    }
    __syncthreads();

    // ---- stage 2: tf32 mma.sync, 16 K-chunks, double-buffered cp.async ----
    float acc[2][16][4];
#pragma unroll
    for (int tm = 0; tm < 2; ++tm)
#pragma unroll
        for (int nt = 0; nt < 16; ++nt)
#pragma unroll
            for (int q = 0; q < 4; ++q) acc[tm][nt][q] = 0.0f;

    for (int c = 0; c < NCHUNK; ++c) {
        if (c == NCHUNK - 1) asm volatile("cp.async.wait_group 0;" ::: "memory");
        else                 asm volatile("cp.async.wait_group 1;" ::: "memory");
        __syncthreads();

        const uint32_t* Bs = (const uint32_t*)(sm + B_OFF + (c & 1) * KCH * BSTRIDE);
#pragma unroll
        for (int ks = 0; ks < 2; ++ks) {
            const int kb = ks * 8;
            uint32_t af[2][4];
#pragma unroll
            for (int tm = 0; tm < 2; ++tm) {
                const uint32_t* ap = Asm + (wr * 32 + tm * 16 + g) * ASTRIDE + c * KCH + kb + tig;
                af[tm][0] = ap[0];
                af[tm][1] = ap[8 * ASTRIDE];
                af[tm][2] = ap[4];
                af[tm][3] = ap[8 * ASTRIDE + 4];
            }
            const uint32_t* bp = Bs + (kb + tig) * BSTRIDE + wc * 128 + g;
#pragma unroll
            for (int nt = 0; nt < 16; ++nt) {
                uint32_t b0 = bp[nt * 8];
                uint32_t b1f = bp[nt * 8 + 4 * BSTRIDE];
                mma_tf32(acc[0][nt], af[0][0], af[0][1], af[0][2], af[0][3], b0, b1f);
                mma_tf32(acc[1][nt], af[1][0], af[1][1], af[1][2], af[1][3], b0, b1f);
            }
        }
        __syncthreads();
        if (c + 2 < NCHUNK) prefetch_chunk(smb, c + 2, c & 1, tid);
    }

    // ---- epilogue: + b2, float2 stores ----
    const size_t task0 = (size_t)blockIdx.x * TASKS;
#pragma unroll
    for (int tm = 0; tm < 2; ++tm) {
        const size_t row0 = task0 + wr * 32 + tm * 16 + g;
#pragma unroll
        for (int nt = 0; nt < 16; ++nt) {
            const int col = wc * 128 + nt * 8 + tig * 2;
            float2 v0, v1;
            v0.x = acc[tm][nt][0] + b2s[col];
            v0.y = acc[tm][nt][1] + b2s[col + 1];
            v1.x = acc[tm][nt][2] + b2s[col];
            v1.y = acc[tm][nt][3] + b2s[col + 1];
            *(float2*)(out + row0 * DDIM + col)       = v0;
            *(float2*)(out + (row0 + 8) * DDIM + col) = v1;
        }
    }
}

extern "C" void kernel_launch(void* const* d_in, const int* in_sizes, int n_in,
                              void* d_out, int out_size)
{
    const int*   y  = (const int*)  d_in[0];
    const float* w1 = (const float*)d_in[1];
    const float* b1 = (const float*)d_in[2];
    const float* w2 = (const float*)d_in[3];
    const float* b2 = (const float*)d_in[4];
    float* out = (float*)d_out;

    const int tasks = in_sizes[0] / 128;
    const int grid  = tasks / TASKS;               // 512 for B=65536

    cudaFuncSetAttribute(tte_main, cudaFuncAttributeMaxDynamicSharedMemorySize, SMEM_BYTES);

    w2_round<<<DDIM * DDIM / 256, 256>>>(w2);
    tte_main<<<grid, THREADS, SMEM_BYTES>>>(y, w1, b1, w2, b2, out);
}

// round 10
// speedup vs baseline: 1.9168x; 1.2784x over previous
#include <cuda_runtime.h>
#include <cstdint>
#include <cstddef>

#define THREADS 256
#define TASKS   64           // tasks per CTA (M)
#define DDIM    256          // N, and K of stage-2
#define SDIM    14
#define KCH     8            // stage-2 K chunk (one k-tile)
#define NCHUNK  (DDIM / KCH) // 32
#define ASTR    72           // AT row stride (floats); 72%32==8 -> frag banks 8*tig+g distinct

// w2 pre-rounded to tf32(rna) and packed in m16n8k8 B-fragment order:
// g_w2f[c*512 + ntp*32 + lane] = { b0(nt=2ntp), b1(nt=2ntp), b0(nt=2ntp+1), b1(nt=2ntp+1) }
// where b0 = w2[c*8+tig][n], b1 = w2[c*8+tig+4][n], n = nt*8+g, g=lane>>2, tig=lane&3.
__device__ float4 g_w2f[NCHUNK * 512];

// ---- smem layout (floats). part aliases AT (disjoint lifetimes). ----
#define AT_OFF   0
#define AT_F     (DDIM * ASTR)          // 18432
#define B_OFF    (AT_OFF + AT_F)        // 2 chunks x 2048 floats
#define B_F      (2 * 2048)
#define W1_OFF   (B_OFF + B_F)          // 22528
#define B1_OFF   (W1_OFF + SDIM * DDIM)
#define B2_OFF   (B1_OFF + DDIM)
#define ST_OFF   (B2_OFF + DDIM)        // stats, stride 17
#define SMEM_F   (ST_OFF + TASKS * 17)  // 27712 floats
#define SMEM_BYTES (SMEM_F * 4)         // 110848 B -> 2 CTAs/SM

static __device__ __forceinline__ uint32_t smem_u32(const void* p) {
    uint32_t a;
    asm("{ .reg .u64 t; cvta.to.shared.u64 t, %1; cvt.u32.u64 %0, t; }"
        : "=r"(a) : "l"(p));
    return a;
}
static __device__ __forceinline__ uint32_t f2tf32(float x) {
    uint32_t u; asm("cvt.rna.tf32.f32 %0, %1;" : "=r"(u) : "f"(x)); return u;
}
static __device__ __forceinline__ void mma_tf32(float* c,
        uint32_t a0, uint32_t a1, uint32_t a2, uint32_t a3,
        float bx, float by) {
    asm volatile("mma.sync.aligned.m16n8k8.row.col.f32.tf32.tf32.f32 "
                 "{%0,%1,%2,%3}, {%4,%5,%6,%7}, {%8,%9}, {%0,%1,%2,%3};"
                 : "+f"(c[0]), "+f"(c[1]), "+f"(c[2]), "+f"(c[3])
                 : "r"(a0), "r"(a1), "r"(a2), "r"(a3),
                   "r"(__float_as_uint(bx)), "r"(__float_as_uint(by)));
}

// ---- prep kernel: rna-round + fragment-pack w2 ----
__global__ void w2_frag(const float* __restrict__ w2) {
    const int tid  = blockIdx.x * 256 + threadIdx.x;    // 0..16383
    const int lane = tid & 31;
    const int ntp  = (tid >> 5) & 15;
    const int c    = tid >> 9;
    const int g    = lane >> 2, tg = lane & 3;
    const int k0   = c * KCH + tg;
    const int n0   = ntp * 16 + g;                      // nt = 2*ntp
    float4 v;
    v.x = __uint_as_float(f2tf32(w2[(k0     ) * DDIM + n0    ]));
    v.y = __uint_as_float(f2tf32(w2[(k0 + 4) * DDIM + n0    ]));
    v.z = __uint_as_float(f2tf32(w2[(k0    ) * DDIM + n0 + 8]));
    v.w = __uint_as_float(f2tf32(w2[(k0 + 4) * DDIM + n0 + 8]));
    g_w2f[tid] = v;
}

// cp.async chunk c (2048 floats, fully contiguous) into buffer b
static __device__ __forceinline__ void prefetch_chunk(uint32_t smb, int c, int b, int tid) {
    const uint32_t dst0 = smb + (uint32_t)(B_OFF + b * 2048) * 4u;
    const float4* src = g_w2f + (size_t)c * 512;
#pragma unroll
    for (int i = 0; i < 2; ++i) {
        int idx = i * THREADS + tid;                    // 0..511 float4s
        asm volatile("cp.async.ca.shared.global [%0], [%1], 16;"
                     :: "r"(dst0 + (uint32_t)idx * 16u), "l"(src + idx));
    }
    asm volatile("cp.async.commit_group;" ::: "memory");
}

__global__ __launch_bounds__(THREADS, 2)
void tte_main(const int*   __restrict__ y,
              const float* __restrict__ w1,
              const float* __restrict__ b1,
              const float* __restrict__ w2,
              const float* __restrict__ b2,
              float*       __restrict__ out)
{
    extern __shared__ float sm[];
    const uint32_t smb = smem_u32(sm);

    uint32_t* AT   = (uint32_t*)(sm + AT_OFF);
    float* w1s     = sm + W1_OFF;
    float* b1s     = sm + B1_OFF;
    float* b2s     = sm + B2_OFF;
    float* statsS  = sm + ST_OFF;
    unsigned long long* part = (unsigned long long*)sm;   // aliases AT (dead by stage 1)

    const int tid  = threadIdx.x;
    const int wid  = tid >> 5, lane = tid & 31;
    const int g    = lane >> 2, tig = lane & 3;
    const int wr   = wid & 1,  wc  = wid >> 1;            // 2 row-groups x 4 col-groups

    // ---- prefetch B chunks 0,1 (overlaps all of phase 1) ----
    prefetch_chunk(smb, 0, 0, tid);
    prefetch_chunk(smb, 1, 1, tid);

    // ---- small params ----
    for (int i = tid; i < SDIM * DDIM; i += THREADS) w1s[i] = w1[i];
    if (tid < DDIM) { b1s[tid] = b1[tid]; b2s[tid] = b2[tid]; }

    // ---- histogram: 4 threads/task, 32 labels each, 6-bit packed u64 ----
    {
        const int t = tid >> 2, sub = tid & 3;
        const int4* yp = (const int4*)(y + ((size_t)blockIdx.x * TASKS + t) * 128 + sub * 32);
        unsigned long long h = 0ULL;
#pragma unroll
        for (int i = 0; i < 8; ++i) {
            int4 v = yp[i];
            h += (1ULL << (6 * v.x)) + (1ULL << (6 * v.y))
               + (1ULL << (6 * v.z)) + (1ULL << (6 * v.w));
        }
        part[t * 4 + sub] = h;
    }
    __syncthreads();

    // ---- stats (threads 0..63, one task each) ----
    if (tid < TASKS) {
        const unsigned long long p0 = part[tid * 4 + 0];
        const unsigned long long p1 = part[tid * 4 + 1];
        const unsigned long long p2 = part[tid * 4 + 2];
        const unsigned long long p3 = part[tid * 4 + 3];
        float pmax = 0.0f, ent = 0.0f; int nnz = 0;
        float* st = &statsS[tid * 17];
#pragma unroll
        for (int c = 0; c < 10; ++c) {
            const int sh = 6 * c;
            int cnt = (int)((p0 >> sh) & 63ULL) + (int)((p1 >> sh) & 63ULL)
                    + (int)((p2 >> sh) & 63ULL) + (int)((p3 >> sh) & 63ULL);
            float p = (float)cnt * (1.0f / 128.0f);       // total is exactly 128
            st[c] = p;
            pmax = fmaxf(pmax, p);
            nnz += (cnt > 0);
            ent -= p * logf(p + 1e-6f);
        }
        st[10] = (float)nnz; st[11] = ent; st[12] = 128.0f; st[13] = pmax;
    }
    __syncthreads();

    // ---- stage 1: exact fp32 FFMA + GELU -> tf32(rna) -> AT[k][t] ----
    {
        const int t = tid & 63, kq = tid >> 6;            // 64 k-values per thread
        float st[SDIM];
#pragma unroll
        for (int i = 0; i < SDIM; ++i) st[i] = statsS[t * 17 + i];
#pragma unroll 4
        for (int j = 0; j < 64; ++j) {
            const int k = kq * 64 + j;
            float v = b1s[k];
#pragma unroll
            for (int i = 0; i < SDIM; ++i) v = fmaf(st[i], w1s[i * DDIM + k], v);
            float gl = 0.5f * v * (1.0f + erff(v * 0.70710678118654752f));
            AT[k * ASTR + t] = f2tf32(gl);                // consecutive t -> conflict-free
        }
    }
    __syncthreads();

    // ---- stage 2: 32 K-chunks, double-buffered, warp tile 32x64 ----
    float acc[2][8][4];
#pragma unroll
    for (int tm = 0; tm < 2; ++tm)
#pragma unroll
        for (int nt = 0; nt < 8; ++nt)
#pragma unroll
            for (int q = 0; q < 4; ++q) acc[tm][nt][q] = 0.0f;

    for (int c = 0; c < NCHUNK; ++c) {
        if (c == NCHUNK - 1) asm volatile("cp.async.wait_group 0;" ::: "memory");
        else                 asm volatile("cp.async.wait_group 1;" ::: "memory");
        __syncthreads();

        // A fragments: banks (8*tig+g)%32 all distinct
        uint32_t af[2][4];
        const uint32_t* a0p = AT + (c * KCH + tig) * ASTR + wr * 32 + g;
#pragma unroll
        for (int tm = 0; tm < 2; ++tm) {
            const uint32_t* ap = a0p + tm * 16;
            af[tm][0] = ap[0];
            af[tm][1] = ap[8];
            af[tm][2] = ap[4 * ASTR];
            af[tm][3] = ap[4 * ASTR + 8];
        }
        const float4* B4 = (const float4*)(sm + B_OFF + (c & 1) * 2048);
#pragma unroll
        for (int p = 0; p < 4; ++p) {
            float4 bf = B4[(wc * 4 + p) * 32 + lane];     // LDS.128, conflict-free
#pragma unroll
            for (int tm = 0; tm < 2; ++tm) {
                mma_tf32(acc[tm][2 * p    ], af[tm][0], af[tm][1], af[tm][2], af[tm][3], bf.x, bf.y);
                mma_tf32(acc[tm][2 * p + 1], af[tm][0], af[tm][1], af[tm][2], af[tm][3], bf.z, bf.w);
            }
        }
        __syncthreads();
        if (c + 2 < NCHUNK) prefetch_chunk(smb, c + 2, c & 1, tid);
    }

    // ---- epilogue: + b2, float2 stores ----
    const size_t task0 = (size_t)blockIdx.x * TASKS;
#pragma unroll
    for (int tm = 0; tm < 2; ++tm) {
        const size_t row = task0 + wr * 32 + tm * 16 + g;
#pragma unroll
        for (int nt = 0; nt < 8; ++nt) {
            const int col = wc * 64 + nt * 8 + tig * 2;
            const float bx = b2s[col], by = b2s[col + 1];
            float2 v0 = { acc[tm][nt][0] + bx, acc[tm][nt][1] + by };
            float2 v1 = { acc[tm][nt][2] + bx, acc[tm][nt][3] + by };
            *(float2*)(out + row * DDIM + col)       = v0;
            *(float2*)(out + (row + 8) * DDIM + col) = v1;
        }
    }
}

extern "C" void kernel_launch(void* const* d_in, const int* in_sizes, int n_in,
                              void* d_out, int out_size)
{
    const int*   y  = (const int*)  d_in[0];
    const float* w1 = (const float*)d_in[1];
    const float* b1 = (const float*)d_in[2];
    const float* w2 = (const float*)d_in[3];
    const float* b2 = (const float*)d_in[4];
    float* out = (float*)d_out;

    const int tasks = in_sizes[0] / 128;
    const int grid  = tasks / TASKS;                      // 1024 for B=65536

    cudaFuncSetAttribute(tte_main, cudaFuncAttributeMaxDynamicSharedMemorySize, SMEM_BYTES);
    cudaFuncSetAttribute(tte_main, cudaFuncAttributePreferredSharedMemoryCarveout, 100);

    w2_frag<<<64, 256>>>(w2);
    tte_main<<<grid, THREADS, SMEM_BYTES>>>(y, w1, b1, w2, b2, out);
}

// round 13
// speedup vs baseline: 2.2150x; 1.1556x over previous
#include <cuda_runtime.h>
#include <cstdint>
#include <cstddef>

#define THREADS 256
#define TASKS   64           // tasks per CTA (M)
#define DDIM    256          // N, and K of stage-2
#define KCH     16           // stage-2 K floats per chunk (2 k-tiles)
#define NCHUNK  (DDIM / KCH) // 16
#define ASTR    72           // AT row stride; 72%32==8 -> frag banks 8*tig+g distinct

// w2 pre-rounded tf32(rna), packed in m16n8k8 B-fragment order (per 8-k tile c8):
// g_w2f[c8*512 + ntp*32 + lane] = {b0(nt=2ntp), b1(nt=2ntp), b0(nt=2ntp+1), b1(nt=2ntp+1)}
// b0 = w2[c8*8+tig][n], b1 = w2[c8*8+tig+4][n], n = nt*8+g.
__device__ float4 g_w2f[32 * 512];
// w1 (14 rows padded to 16) packed identically: 2 k-tiles.
__device__ float4 g_w1f[2 * 512];

// ---- smem layout (floats). part aliases AT (disjoint lifetimes). ----
#define AT_OFF   0
#define AT_F     (DDIM * ASTR)           // 18432
#define B_OFF    (AT_OFF + AT_F)
#define B_F      (2 * 4096)              // 2 chunks x (2 k-tiles x 2048 floats)
#define B1_OFF   (B_OFF + B_F)
#define B2_OFF   (B1_OFF + DDIM)
#define ST_OFF   (B2_OFF + DDIM)         // stats [64][17], tf32-rounded, k-padded
#define SMEM_F   (ST_OFF + TASKS * 17)
#define SMEM_BYTES (SMEM_F * 4)          // 112896 B -> 2 CTAs/SM

static __device__ __forceinline__ uint32_t smem_u32(const void* p) {
    uint32_t a;
    asm("{ .reg .u64 t; cvta.to.shared.u64 t, %1; cvt.u32.u64 %0, t; }"
        : "=r"(a) : "l"(p));
    return a;
}
static __device__ __forceinline__ uint32_t f2tf32(float x) {
    uint32_t u; asm("cvt.rna.tf32.f32 %0, %1;" : "=r"(u) : "f"(x)); return u;
}
static __device__ __forceinline__ void mma_tf32(float* c,
        uint32_t a0, uint32_t a1, uint32_t a2, uint32_t a3,
        float bx, float by) {
    asm volatile("mma.sync.aligned.m16n8k8.row.col.f32.tf32.tf32.f32 "
                 "{%0,%1,%2,%3}, {%4,%5,%6,%7}, {%8,%9}, {%0,%1,%2,%3};"
                 : "+f"(c[0]), "+f"(c[1]), "+f"(c[2]), "+f"(c[3])
                 : "r"(a0), "r"(a1), "r"(a2), "r"(a3),
                   "r"(__float_as_uint(bx)), "r"(__float_as_uint(by)));
}

// ---- prep kernel: rna-round + fragment-pack w2 (blocks 0..63) and w1 (block 64) ----
__global__ void w_frag(const float* __restrict__ w1, const float* __restrict__ w2) {
    if (blockIdx.x < 64) {
        const int tid  = blockIdx.x * 256 + threadIdx.x;   // 0..16383
        const int lane = tid & 31;
        const int ntp  = (tid >> 5) & 15;
        const int c8   = tid >> 9;
        const int g = lane >> 2, tg = lane & 3;
        const int k0 = c8 * 8 + tg;
        const int n0 = ntp * 16 + g;
        float4 v;
        v.x = __uint_as_float(f2tf32(w2[(k0    ) * DDIM + n0    ]));
        v.y = __uint_as_float(f2tf32(w2[(k0 + 4) * DDIM + n0    ]));
        v.z = __uint_as_float(f2tf32(w2[(k0    ) * DDIM + n0 + 8]));
        v.w = __uint_as_float(f2tf32(w2[(k0 + 4) * DDIM + n0 + 8]));
        g_w2f[tid] = v;
    } else {
#pragma unroll
        for (int e = 0; e < 4; ++e) {
            const int idx  = e * 256 + threadIdx.x;        // 0..1023
            const int lane = idx & 31;
            const int ntp  = (idx >> 5) & 15;
            const int c    = idx >> 9;                     // k-tile 0..1
            const int g = lane >> 2, tg = lane & 3;
            const int k0 = c * 8 + tg;                     // <= 11
            const int n0 = ntp * 16 + g;
            float4 v;
            v.x = __uint_as_float(f2tf32(w1[k0 * DDIM + n0]));
            v.y = (k0 + 4 < 14) ? __uint_as_float(f2tf32(w1[(k0 + 4) * DDIM + n0])) : 0.0f;
            v.z = __uint_as_float(f2tf32(w1[k0 * DDIM + n0 + 8]));
            v.w = (k0 + 4 < 14) ? __uint_as_float(f2tf32(w1[(k0 + 4) * DDIM + n0 + 8])) : 0.0f;
            g_w1f[idx] = v;
        }
    }
}

// cp.async stage-2 chunk c (2 k-tiles = 1024 float4, contiguous) into buffer b
static __device__ __forceinline__ void prefetch_chunk(uint32_t smb, int c, int b, int tid) {
    const uint32_t dst0 = smb + (uint32_t)(B_OFF + b * 4096) * 4u;
    const float4* src = g_w2f + (size_t)c * 1024;
#pragma unroll
    for (int i = 0; i < 4; ++i) {
        int idx = i * THREADS + tid;                       // 0..1023
        asm volatile("cp.async.ca.shared.global [%0], [%1], 16;"
                     :: "r"(dst0 + (uint32_t)idx * 16u), "l"(src + idx));
    }
    asm volatile("cp.async.commit_group;" ::: "memory");
}

__global__ __launch_bounds__(THREADS, 2)
void tte_main(const int*   __restrict__ y,
              const float* __restrict__ w1,
              const float* __restrict__ b1,
              const float* __restrict__ w2,
              const float* __restrict__ b2,
              float*       __restrict__ out)
{
    extern __shared__ float sm[];
    const uint32_t smb = smem_u32(sm);

    uint32_t* AT      = (uint32_t*)(sm + AT_OFF);
    float*    b1s     = sm + B1_OFF;
    float*    b2s     = sm + B2_OFF;
    float*    statsS  = sm + ST_OFF;
    const uint32_t* statsU = (const uint32_t*)statsS;
    unsigned long long* part = (unsigned long long*)sm;    // aliases AT (dead by stage 1)

    const int tid  = threadIdx.x;
    const int wid  = tid >> 5, lane = tid & 31;
    const int g    = lane >> 2, tig = lane & 3;
    const int wr   = wid & 1,  wc  = wid >> 1;             // 2 row-groups x 4 col-groups

    // ---- prefetch stage-2 B chunks 0,1 (overlaps all of phase 1) ----
    prefetch_chunk(smb, 0, 0, tid);
    prefetch_chunk(smb, 1, 1, tid);

    // ---- biases ----
    b1s[tid] = b1[tid];
    b2s[tid] = b2[tid];

    // ---- histogram: 4 threads/task, 32 labels each, 6-bit packed u64 ----
    {
        const int t = tid >> 2, sub = tid & 3;
        const int4* yp = (const int4*)(y + ((size_t)blockIdx.x * TASKS + t) * 128 + sub * 32);
        unsigned long long h = 0ULL;
#pragma unroll
        for (int i = 0; i < 8; ++i) {
            int4 v = yp[i];
            h += (1ULL << (6 * v.x)) + (1ULL << (6 * v.y))
               + (1ULL << (6 * v.z)) + (1ULL << (6 * v.w));
        }
        part[t * 4 + sub] = h;
    }
    __syncthreads();

    // ---- stats (threads 0..63, one task each), tf32-rounded, k-padded ----
    if (tid < TASKS) {
        const unsigned long long p0 = part[tid * 4 + 0];
        const unsigned long long p1 = part[tid * 4 + 1];
        const unsigned long long p2 = part[tid * 4 + 2];
        const unsigned long long p3 = part[tid * 4 + 3];
        float pmax = 0.0f, ent = 0.0f; int nnz = 0;
        uint32_t* st = (uint32_t*)&statsS[tid * 17];
#pragma unroll
        for (int c = 0; c < 10; ++c) {
            const int sh = 6 * c;
            int cnt = (int)((p0 >> sh) & 63ULL) + (int)((p1 >> sh) & 63ULL)
                    + (int)((p2 >> sh) & 63ULL) + (int)((p3 >> sh) & 63ULL);
            float p = (float)cnt * (1.0f / 128.0f);        // exact in tf32
            st[c] = __float_as_uint(p);
            pmax = fmaxf(pmax, p);
            nnz += (cnt > 0);
            ent -= p * logf(p + 1e-6f);
        }
        st[10] = __float_as_uint((float)nnz);
        st[11] = f2tf32(ent);                              // only inexact stat
        st[12] = __float_as_uint(128.0f);
        st[13] = __float_as_uint(pmax);
        st[14] = 0u; st[15] = 0u;                          // K padding
    }
    __syncthreads();

    // ---- stage 1 via tf32 mma: h1 = GELU(stats @ w1 + b1) -> tf32 -> AT[k][t] ----
    {
        // stats A-fragments (smem, stride 17 -> <=2-way conflicts, 16 loads)
        uint32_t sf[2][2][4];                              // [ktile][tm][reg]
#pragma unroll
        for (int kt = 0; kt < 2; ++kt)
#pragma unroll
            for (int tm = 0; tm < 2; ++tm) {
                const uint32_t* sp = statsU + (wr * 32 + tm * 16 + g) * 17 + kt * 8 + tig;
                sf[kt][tm][0] = sp[0];
                sf[kt][tm][1] = sp[8 * 17];
                sf[kt][tm][2] = sp[4];
                sf[kt][tm][3] = sp[8 * 17 + 4];
            }
        // w1 B-fragments straight from L2
        float4 wb[2][4];
#pragma unroll
        for (int kt = 0; kt < 2; ++kt)
#pragma unroll
            for (int p = 0; p < 4; ++p)
                wb[kt][p] = g_w1f[kt * 512 + (wc * 4 + p) * 32 + lane];

#pragma unroll
        for (int tm = 0; tm < 2; ++tm) {
            float a1[8][4];
#pragma unroll
            for (int nt = 0; nt < 8; ++nt)
#pragma unroll
                for (int q = 0; q < 4; ++q) a1[nt][q] = 0.0f;
#pragma unroll
            for (int kt = 0; kt < 2; ++kt)
#pragma unroll
                for (int p = 0; p < 4; ++p) {
                    const float4 bf = wb[kt][p];
                    mma_tf32(a1[2 * p    ], sf[kt][tm][0], sf[kt][tm][1], sf[kt][tm][2], sf[kt][tm][3], bf.x, bf.y);
                    mma_tf32(a1[2 * p + 1], sf[kt][tm][0], sf[kt][tm][1], sf[kt][tm][2], sf[kt][tm][3], bf.z, bf.w);
                }
            const int row = wr * 32 + tm * 16 + g;
#pragma unroll
            for (int nt = 0; nt < 8; ++nt) {
                const int col = wc * 64 + nt * 8 + 2 * tig;
                const float bx = b1s[col], by = b1s[col + 1];
                float v0 = a1[nt][0] + bx, v1 = a1[nt][1] + by;
                float v2 = a1[nt][2] + bx, v3 = a1[nt][3] + by;
                v0 = 0.5f * v0 * (1.0f + erff(v0 * 0.70710678118654752f));
                v1 = 0.5f * v1 * (1.0f + erff(v1 * 0.70710678118654752f));
                v2 = 0.5f * v2 * (1.0f + erff(v2 * 0.70710678118654752f));
                v3 = 0.5f * v3 * (1.0f + erff(v3 * 0.70710678118654752f));
                AT[(col    ) * ASTR + row    ] = f2tf32(v0);
                AT[(col + 1) * ASTR + row    ] = f2tf32(v1);
                AT[(col    ) * ASTR + row + 8] = f2tf32(v2);
                AT[(col + 1) * ASTR + row + 8] = f2tf32(v3);
            }
        }
    }
    // (first mainloop iteration's barrier publishes AT to all warps)

    // ---- stage 2: 16 K-chunks (2 k-tiles each), double-buffered ----
    float acc[2][8][4];
#pragma unroll
    for (int tm = 0; tm < 2; ++tm)
#pragma unroll
        for (int nt = 0; nt < 8; ++nt)
#pragma unroll
            for (int q = 0; q < 4; ++q) acc[tm][nt][q] = 0.0f;

    for (int c = 0; c < NCHUNK; ++c) {
        if (c == NCHUNK - 1) asm volatile("cp.async.wait_group 0;" ::: "memory");
        else                 asm volatile("cp.async.wait_group 1;" ::: "memory");
        __syncthreads();

        const float4* B4 = (const float4*)(sm + B_OFF + (c & 1) * 4096);
#pragma unroll
        for (int kt = 0; kt < 2; ++kt) {
            const int c8 = 2 * c + kt;
            uint32_t af[2][4];
            const uint32_t* a0p = AT + (c8 * 8 + tig) * ASTR + wr * 32 + g;
#pragma unroll
            for (int tm = 0; tm < 2; ++tm) {
                const uint32_t* ap = a0p + tm * 16;
                af[tm][0] = ap[0];
                af[tm][1] = ap[8];
                af[tm][2] = ap[4 * ASTR];
                af[tm][3] = ap[4 * ASTR + 8];
            }
#pragma unroll
            for (int p = 0; p < 4; ++p) {
                const float4 bf = B4[kt * 512 + (wc * 4 + p) * 32 + lane];
#pragma unroll
                for (int tm = 0; tm < 2; ++tm) {
                    mma_tf32(acc[tm][2 * p    ], af[tm][0], af[tm][1], af[tm][2], af[tm][3], bf.x, bf.y);
                    mma_tf32(acc[tm][2 * p + 1], af[tm][0], af[tm][1], af[tm][2], af[tm][3], bf.z, bf.w);
                }
            }
        }
        __syncthreads();
        if (c + 2 < NCHUNK) prefetch_chunk(smb, c + 2, c & 1, tid);
    }

    // ---- epilogue: + b2, float2 stores ----
    const size_t task0 = (size_t)blockIdx.x * TASKS;
#pragma unroll
    for (int tm = 0; tm < 2; ++tm) {
        const size_t row = task0 + wr * 32 + tm * 16 + g;
#pragma unroll
        for (int nt = 0; nt < 8; ++nt) {
            const int col = wc * 64 + nt * 8 + tig * 2;
            const float bx = b2s[col], by = b2s[col + 1];
            float2 v0 = { acc[tm][nt][0] + bx, acc[tm][nt][1] + by };
            float2 v1 = { acc[tm][nt][2] + bx, acc[tm][nt][3] + by };
            *(float2*)(out + row * DDIM + col)       = v0;
            *(float2*)(out + (row + 8) * DDIM + col) = v1;
        }
    }
}

extern "C" void kernel_launch(void* const* d_in, const int* in_sizes, int n_in,
                              void* d_out, int out_size)
{
    const int*   y  = (const int*)  d_in[0];
    const float* w1 = (const float*)d_in[1];
    const float* b1 = (const float*)d_in[2];
    const float* w2 = (const float*)d_in[3];
    const float* b2 = (const float*)d_in[4];
    float* out = (float*)d_out;

    const int tasks = in_sizes[0] / 128;
    const int grid  = tasks / TASKS;                       // 1024 for B=65536

    cudaFuncSetAttribute(tte_main, cudaFuncAttributeMaxDynamicSharedMemorySize, SMEM_BYTES);
    cudaFuncSetAttribute(tte_main, cudaFuncAttributePreferredSharedMemoryCarveout, 100);

    w_frag<<<65, 256>>>(w1, w2);
    tte_main<<<grid, THREADS, SMEM_BYTES>>>(y, w1, b1, w2, b2, out);
}

// round 15
// speedup vs baseline: 2.8998x; 1.3092x over previous
#include <cuda_runtime.h>
#include <cstdint>
#include <cstddef>

#define THREADS 256
#define TASKS   64           // tasks per CTA (M)
#define DDIM    256          // N, and K of stage-2
#define ASTR    72           // AT row stride; 72%32==8 -> frag banks 8*tig+g distinct

// w2 pre-rounded tf32(rna), packed in m16n8k8 B-fragment order (per 8-k tile c8):
// g_w2f[c8*512 + ntp*32 + lane] = {b0(nt=2ntp), b1(nt=2ntp), b0(nt=2ntp+1), b1(nt=2ntp+1)}
// b0 = w2[c8*8+tig][n], b1 = w2[c8*8+tig+4][n], n = nt*8+g.
__device__ float4 g_w2f[32 * 512];
// w1 (14 rows padded to 16) packed identically: 2 k-tiles.
__device__ float4 g_w1f[2 * 512];

// ---- smem layout (floats). part aliases AT (disjoint lifetimes). ----
#define AT_OFF   0
#define AT_F     (DDIM * ASTR)           // 18432
#define B1_OFF   (AT_OFF + AT_F)
#define B2_OFF   (B1_OFF + DDIM)
#define ST_OFF   (B2_OFF + DDIM)         // stats [64][17], tf32-rounded, k-padded
#define SMEM_F   (ST_OFF + TASKS * 17)
#define SMEM_BYTES (SMEM_F * 4)          // 80128 B -> 2 CTAs/SM

static __device__ __forceinline__ uint32_t f2tf32(float x) {
    uint32_t u; asm("cvt.rna.tf32.f32 %0, %1;" : "=r"(u) : "f"(x)); return u;
}
static __device__ __forceinline__ void mma_tf32(float* c,
        uint32_t a0, uint32_t a1, uint32_t a2, uint32_t a3,
        float bx, float by) {
    asm volatile("mma.sync.aligned.m16n8k8.row.col.f32.tf32.tf32.f32 "
                 "{%0,%1,%2,%3}, {%4,%5,%6,%7}, {%8,%9}, {%0,%1,%2,%3};"
                 : "+f"(c[0]), "+f"(c[1]), "+f"(c[2]), "+f"(c[3])
                 : "r"(a0), "r"(a1), "r"(a2), "r"(a3),
                   "r"(__float_as_uint(bx)), "r"(__float_as_uint(by)));
}

// ---- prep kernel: rna-round + fragment-pack w2 (blocks 0..63) and w1 (block 64) ----
__global__ void w_frag(const float* __restrict__ w1, const float* __restrict__ w2) {
    if (blockIdx.x < 64) {
        const int tid  = blockIdx.x * 256 + threadIdx.x;   // 0..16383
        const int lane = tid & 31;
        const int ntp  = (tid >> 5) & 15;
        const int c8   = tid >> 9;
        const int g = lane >> 2, tg = lane & 3;
        const int k0 = c8 * 8 + tg;
        const int n0 = ntp * 16 + g;
        float4 v;
        v.x = __uint_as_float(f2tf32(w2[(k0    ) * DDIM + n0    ]));
        v.y = __uint_as_float(f2tf32(w2[(k0 + 4) * DDIM + n0    ]));
        v.z = __uint_as_float(f2tf32(w2[(k0    ) * DDIM + n0 + 8]));
        v.w = __uint_as_float(f2tf32(w2[(k0 + 4) * DDIM + n0 + 8]));
        g_w2f[tid] = v;
    } else {
#pragma unroll
        for (int e = 0; e < 4; ++e) {
            const int idx  = e * 256 + threadIdx.x;        // 0..1023
            const int lane = idx & 31;
            const int ntp  = (idx >> 5) & 15;
            const int c    = idx >> 9;                     // k-tile 0..1
            const int g = lane >> 2, tg = lane & 3;
            const int k0 = c * 8 + tg;                     // <= 11
            const int n0 = ntp * 16 + g;
            float4 v;
            v.x = __uint_as_float(f2tf32(w1[k0 * DDIM + n0]));
            v.y = (k0 + 4 < 14) ? __uint_as_float(f2tf32(w1[(k0 + 4) * DDIM + n0])) : 0.0f;
            v.z = __uint_as_float(f2tf32(w1[k0 * DDIM + n0 + 8]));
            v.w = (k0 + 4 < 14) ? __uint_as_float(f2tf32(w1[(k0 + 4) * DDIM + n0 + 8])) : 0.0f;
            g_w1f[idx] = v;
        }
    }
}

__global__ __launch_bounds__(THREADS, 2)
void tte_main(const int*   __restrict__ y,
              const float* __restrict__ w1,
              const float* __restrict__ b1,
              const float* __restrict__ w2,
              const float* __restrict__ b2,
              float*       __restrict__ out)
{
    extern __shared__ float sm[];

    uint32_t* AT      = (uint32_t*)(sm + AT_OFF);
    float*    b1s     = sm + B1_OFF;
    float*    b2s     = sm + B2_OFF;
    float*    statsS  = sm + ST_OFF;
    const uint32_t* statsU = (const uint32_t*)statsS;
    unsigned long long* part = (unsigned long long*)sm;    // aliases AT (dead by stage 1)

    const int tid  = threadIdx.x;
    const int wid  = tid >> 5, lane = tid & 31;
    const int g    = lane >> 2, tig = lane & 3;
    const int wr   = wid & 1,  wc  = wid >> 1;             // 2 row-groups x 4 col-groups

    // ---- biases ----
    b1s[tid] = b1[tid];
    b2s[tid] = b2[tid];

    // ---- histogram: 4 threads/task, 32 labels each, 6-bit packed u64 ----
    {
        const int t = tid >> 2, sub = tid & 3;
        const int4* yp = (const int4*)(y + ((size_t)blockIdx.x * TASKS + t) * 128 + sub * 32);
        unsigned long long h = 0ULL;
#pragma unroll
        for (int i = 0; i < 8; ++i) {
            int4 v = yp[i];
            h += (1ULL << (6 * v.x)) + (1ULL << (6 * v.y))
               + (1ULL << (6 * v.z)) + (1ULL << (6 * v.w));
        }
        part[t * 4 + sub] = h;
    }
    __syncthreads();

    // ---- stats (threads 0..63, one task each), tf32-rounded, k-padded ----
    if (tid < TASKS) {
        const unsigned long long p0 = part[tid * 4 + 0];
        const unsigned long long p1 = part[tid * 4 + 1];
        const unsigned long long p2 = part[tid * 4 + 2];
        const unsigned long long p3 = part[tid * 4 + 3];
        float pmax = 0.0f, ent = 0.0f; int nnz = 0;
        uint32_t* st = (uint32_t*)&statsS[tid * 17];
#pragma unroll
        for (int c = 0; c < 10; ++c) {
            const int sh = 6 * c;
            int cnt = (int)((p0 >> sh) & 63ULL) + (int)((p1 >> sh) & 63ULL)
                    + (int)((p2 >> sh) & 63ULL) + (int)((p3 >> sh) & 63ULL);
            float p = (float)cnt * (1.0f / 128.0f);        // exact in tf32
            st[c] = __float_as_uint(p);
            pmax = fmaxf(pmax, p);
            nnz += (cnt > 0);
            ent -= p * logf(p + 1e-6f);
        }
        st[10] = __float_as_uint((float)nnz);
        st[11] = f2tf32(ent);                              // only inexact stat
        st[12] = __float_as_uint(128.0f);
        st[13] = __float_as_uint(pmax);
        st[14] = 0u; st[15] = 0u;                          // K padding
    }
    __syncthreads();

    // ---- stage 1 via tf32 mma: h1 = GELU(stats @ w1 + b1) -> tf32 -> AT[k][t] ----
    {
        uint32_t sf[2][2][4];                              // [ktile][tm][reg]
#pragma unroll
        for (int kt = 0; kt < 2; ++kt)
#pragma unroll
            for (int tm = 0; tm < 2; ++tm) {
                const uint32_t* sp = statsU + (wr * 32 + tm * 16 + g) * 17 + kt * 8 + tig;
                sf[kt][tm][0] = sp[0];
                sf[kt][tm][1] = sp[8 * 17];
                sf[kt][tm][2] = sp[4];
                sf[kt][tm][3] = sp[8 * 17 + 4];
            }
        float4 wb[2][4];
#pragma unroll
        for (int kt = 0; kt < 2; ++kt)
#pragma unroll
            for (int p = 0; p < 4; ++p)
                wb[kt][p] = g_w1f[kt * 512 + (wc * 4 + p) * 32 + lane];

#pragma unroll
        for (int tm = 0; tm < 2; ++tm) {
            float a1[8][4];
#pragma unroll
            for (int nt = 0; nt < 8; ++nt)
#pragma unroll
                for (int q = 0; q < 4; ++q) a1[nt][q] = 0.0f;
#pragma unroll
            for (int kt = 0; kt < 2; ++kt)
#pragma unroll
                for (int p = 0; p < 4; ++p) {
                    const float4 bf = wb[kt][p];
                    mma_tf32(a1[2 * p    ], sf[kt][tm][0], sf[kt][tm][1], sf[kt][tm][2], sf[kt][tm][3], bf.x, bf.y);
                    mma_tf32(a1[2 * p + 1], sf[kt][tm][0], sf[kt][tm][1], sf[kt][tm][2], sf[kt][tm][3], bf.z, bf.w);
                }
            const int row = wr * 32 + tm * 16 + g;
#pragma unroll
            for (int nt = 0; nt < 8; ++nt) {
                const int col = wc * 64 + nt * 8 + 2 * tig;
                const float bx = b1s[col], by = b1s[col + 1];
                float v0 = a1[nt][0] + bx, v1 = a1[nt][1] + by;
                float v2 = a1[nt][2] + bx, v3 = a1[nt][3] + by;
                v0 = 0.5f * v0 * (1.0f + erff(v0 * 0.70710678118654752f));
                v1 = 0.5f * v1 * (1.0f + erff(v1 * 0.70710678118654752f));
                v2 = 0.5f * v2 * (1.0f + erff(v2 * 0.70710678118654752f));
                v3 = 0.5f * v3 * (1.0f + erff(v3 * 0.70710678118654752f));
                AT[(col    ) * ASTR + row    ] = f2tf32(v0);
                AT[(col + 1) * ASTR + row    ] = f2tf32(v1);
                AT[(col    ) * ASTR + row + 8] = f2tf32(v2);
                AT[(col + 1) * ASTR + row + 8] = f2tf32(v3);
            }
        }
    }
    __syncthreads();                                       // publish AT; last barrier

    // ---- stage 2: 32 k-tiles, barrier-free, B frags LDG'd from L2, depth-2 pipeline ----
    float acc[2][8][4];
#pragma unroll
    for (int tm = 0; tm < 2; ++tm)
#pragma unroll
        for (int nt = 0; nt < 8; ++nt)
#pragma unroll
            for (int q = 0; q < 4; ++q) acc[tm][nt][q] = 0.0f;

    const float4* wptr = g_w2f + wc * 128 + lane;          // + c8*512 + p*32
    float4 bf[2][4];
#pragma unroll
    for (int p = 0; p < 4; ++p) bf[0][p] = wptr[p * 32];

#pragma unroll
    for (int c8 = 0; c8 < 32; ++c8) {
        if (c8 + 1 < 32) {
#pragma unroll
            for (int p = 0; p < 4; ++p)
                bf[(c8 + 1) & 1][p] = wptr[(c8 + 1) * 512 + p * 32];
        }
        uint32_t af[2][4];
        const uint32_t* a0p = AT + (c8 * 8 + tig) * ASTR + wr * 32 + g;
#pragma unroll
        for (int tm = 0; tm < 2; ++tm) {
            const uint32_t* ap = a0p + tm * 16;
            af[tm][0] = ap[0];
            af[tm][1] = ap[8];
            af[tm][2] = ap[4 * ASTR];
            af[tm][3] = ap[4 * ASTR + 8];
        }
        const float4* bc = bf[c8 & 1];
#pragma unroll
        for (int p = 0; p < 4; ++p) {
#pragma unroll
            for (int tm = 0; tm < 2; ++tm) {
                mma_tf32(acc[tm][2 * p    ], af[tm][0], af[tm][1], af[tm][2], af[tm][3], bc[p].x, bc[p].y);
                mma_tf32(acc[tm][2 * p + 1], af[tm][0], af[tm][1], af[tm][2], af[tm][3], bc[p].z, bc[p].w);
            }
        }
    }

    // ---- epilogue: + b2, float2 stores ----
    const size_t task0 = (size_t)blockIdx.x * TASKS;
#pragma unroll
    for (int tm = 0; tm < 2; ++tm) {
        const size_t row = task0 + wr * 32 + tm * 16 + g;
#pragma unroll
        for (int nt = 0; nt < 8; ++nt) {
            const int col = wc * 64 + nt * 8 + tig * 2;
            const float bx = b2s[col], by = b2s[col + 1];
            float2 v0 = { acc[tm][nt][0] + bx, acc[tm][nt][1] + by };
            float2 v1 = { acc[tm][nt][2] + bx, acc[tm][nt][3] + by };
            *(float2*)(out + row * DDIM + col)       = v0;
            *(float2*)(out + (row + 8) * DDIM + col) = v1;
        }
    }
}

extern "C" void kernel_launch(void* const* d_in, const int* in_sizes, int n_in,
                              void* d_out, int out_size)
{
    const int*   y  = (const int*)  d_in[0];
    const float* w1 = (const float*)d_in[1];
    const float* b1 = (const float*)d_in[2];
    const float* w2 = (const float*)d_in[3];
    const float* b2 = (const float*)d_in[4];
    float* out = (float*)d_out;

    const int tasks = in_sizes[0] / 128;
    const int grid  = tasks / TASKS;                       // 1024 for B=65536

    cudaFuncSetAttribute(tte_main, cudaFuncAttributeMaxDynamicSharedMemorySize, SMEM_BYTES);
    cudaFuncSetAttribute(tte_main, cudaFuncAttributePreferredSharedMemoryCarveout, 100);

    w_frag<<<65, 256>>>(w1, w2);
    tte_main<<<grid, THREADS, SMEM_BYTES>>>(y, w1, b1, w2, b2, out);
}